// round 1
// baseline (speedup 1.0000x reference)
#include <cuda_runtime.h>
#include <math.h>

#define BB 4
#define NDET 128
#define NT 2048
#define NY 256
#define NX 256
#define DD 256
#define LL 6
#define NHH 8
#define PSZ 16
#define NTOK 256
#define MTOK 1024
#define HD 32
#define IMG (BB*NY*NX)

// ---------------- scratch (device globals; no allocation allowed) ----------
__device__ float g_bp  [IMG];
__device__ float g_x   [MTOK*DD];
__device__ float g_z   [MTOK*DD];
__device__ float g_y   [MTOK*DD];
__device__ float g_qkv [MTOK*3*DD];
__device__ float g_att [MTOK*DD];
__device__ float g_h1  [MTOK*4*DD];
__device__ float g_pix [MTOK*DD];
__device__ float g_img [IMG];

// ---------------- backprojection: one warp per pixel, lanes over detectors -
__global__ void bp_kernel(const float* __restrict__ sino,
                          const float* __restrict__ lut,
                          float* __restrict__ out_bp) {
    int gw   = (blockIdx.x * blockDim.x + threadIdx.x) >> 5;   // pixel = y*NX+x
    int lane = threadIdx.x & 31;
    if (gw >= NY * NX) return;
    float acc0 = 0.f, acc1 = 0.f, acc2 = 0.f, acc3 = 0.f;
    const float2* l2 = (const float2*)lut;
#pragma unroll
    for (int dd = 0; dd < 4; dd++) {
        int d = lane + dd * 32;
        float2 ka = l2[(size_t)gw * NDET + d];        // (kf, alpha) coalesced
        int   kf    = (int)ka.x;
        if (kf >= 0 && kf < NT - 1) {
            float alpha = ka.y;
            float apod  = 0.5f - 0.5f * cosf(6.283185307179586f * (float)d / 127.0f);
            const float* sp = sino + (size_t)d * NT + kf;
            {
                float s0 = sp[0*NDET*NT], s1 = sp[0*NDET*NT+1];
                acc0 += apod * ((1.0f - alpha) * s0 + alpha * s1);
            }
            {
                float s0 = sp[1*NDET*NT], s1 = sp[1*NDET*NT+1];
                acc1 += apod * ((1.0f - alpha) * s0 + alpha * s1);
            }
            {
                float s0 = sp[2*NDET*NT], s1 = sp[2*NDET*NT+1];
                acc2 += apod * ((1.0f - alpha) * s0 + alpha * s1);
            }
            {
                float s0 = sp[3*NDET*NT], s1 = sp[3*NDET*NT+1];
                acc3 += apod * ((1.0f - alpha) * s0 + alpha * s1);
            }
        }
    }
#pragma unroll
    for (int o = 16; o; o >>= 1) {
        acc0 += __shfl_xor_sync(0xffffffffu, acc0, o);
        acc1 += __shfl_xor_sync(0xffffffffu, acc1, o);
        acc2 += __shfl_xor_sync(0xffffffffu, acc2, o);
        acc3 += __shfl_xor_sync(0xffffffffu, acc3, o);
    }
    if (lane == 0) {
        const float inv = 1.0f / 63.5f;   // sum_{d=0}^{127} (0.5-0.5cos(2pi d/127)) = 63.5
        float v0 = acc0 * inv, v1 = acc1 * inv, v2 = acc2 * inv, v3 = acc3 * inv;
        g_bp[0*NY*NX + gw] = v0;
        g_bp[1*NY*NX + gw] = v1;
        g_bp[2*NY*NX + gw] = v2;
        g_bp[3*NY*NX + gw] = v3;
        if (out_bp) {
            out_bp[0*NY*NX + gw] = v0;
            out_bp[1*NY*NX + gw] = v1;
            out_bp[2*NY*NX + gw] = v2;
            out_bp[3*NY*NX + gw] = v3;
        }
    }
}

// ---------------- patchify: bp image -> (B*N, 256) patch rows --------------
__global__ void patchify_kernel() {
    int idx = blockIdx.x * blockDim.x + threadIdx.x;
    if (idx >= MTOK * DD) return;
    int px = idx & 15, py = (idx >> 4) & 15, wp = (idx >> 8) & 15,
        hp = (idx >> 12) & 15, b = idx >> 16;
    g_x[idx] = g_bp[b * (NY * NX) + (hp * 16 + py) * NX + (wp * 16 + px)];
}

// ---------------- generic fp32 GEMM: C = A[M,K] @ W[N,K]^T + bias ----------
// mode 0: store   1: store gelu(exact)   2: C += result   3: + pos_embed
__global__ void gemm_kernel(const float* __restrict__ A,
                            const float* __restrict__ W,
                            const float* __restrict__ bias,
                            float* __restrict__ C,
                            const float* __restrict__ pos,
                            int M, int Nn, int K, int mode) {
    __shared__ float As[16][68];
    __shared__ float Ws[16][68];
    int tid = threadIdx.x;
    int tx = tid & 15, ty = tid >> 4;
    int row0 = blockIdx.y * 64, col0 = blockIdx.x * 64;
    float acc[4][4];
#pragma unroll
    for (int i = 0; i < 4; i++)
#pragma unroll
        for (int j = 0; j < 4; j++) acc[i][j] = 0.f;

    for (int k0 = 0; k0 < K; k0 += 16) {
#pragma unroll
        for (int i = 0; i < 4; i++) {
            int idx = tid + i * 256;
            int r = idx >> 4, c = idx & 15;
            As[c][r] = A[(size_t)(row0 + r) * K + k0 + c];
            Ws[c][r] = W[(size_t)(col0 + r) * K + k0 + c];
        }
        __syncthreads();
#pragma unroll
        for (int kk = 0; kk < 16; kk++) {
            float a[4], w[4];
#pragma unroll
            for (int i = 0; i < 4; i++) a[i] = As[kk][ty * 4 + i];
#pragma unroll
            for (int j = 0; j < 4; j++) w[j] = Ws[kk][tx * 4 + j];
#pragma unroll
            for (int i = 0; i < 4; i++)
#pragma unroll
                for (int j = 0; j < 4; j++) acc[i][j] += a[i] * w[j];
        }
        __syncthreads();
    }
#pragma unroll
    for (int i = 0; i < 4; i++) {
        int r = row0 + ty * 4 + i;
#pragma unroll
        for (int j = 0; j < 4; j++) {
            int c = col0 + tx * 4 + j;
            float v = acc[i][j] + bias[c];
            if (mode == 3) v += pos[(size_t)(r & (NTOK - 1)) * Nn + c];
            if (mode == 1) v = 0.5f * v * (1.0f + erff(v * 0.7071067811865475f));
            if (mode == 2) C[(size_t)r * Nn + c] += v;
            else           C[(size_t)r * Nn + c] = v;
        }
    }
}

// ---------------- layernorm: one block per token row ------------------------
__global__ void ln_kernel(const float* __restrict__ in,
                          const float* __restrict__ gam,
                          const float* __restrict__ bet,
                          float* __restrict__ out) {
    __shared__ float red[8];
    int row = blockIdx.x, t = threadIdx.x;
    float x = in[(size_t)row * DD + t];
    float s = x;
#pragma unroll
    for (int o = 16; o; o >>= 1) s += __shfl_xor_sync(0xffffffffu, s, o);
    if ((t & 31) == 0) red[t >> 5] = s;
    __syncthreads();
    float tot = red[0]+red[1]+red[2]+red[3]+red[4]+red[5]+red[6]+red[7];
    float mean = tot * (1.0f / DD);
    float d = x - mean;
    float sq = d * d;
#pragma unroll
    for (int o = 16; o; o >>= 1) sq += __shfl_xor_sync(0xffffffffu, sq, o);
    __syncthreads();
    if ((t & 31) == 0) red[t >> 5] = sq;
    __syncthreads();
    float var = (red[0]+red[1]+red[2]+red[3]+red[4]+red[5]+red[6]+red[7]) * (1.0f / DD);
    out[(size_t)row * DD + t] = d * rsqrtf(var + 1e-5f) * gam[t] + bet[t];
}

// ---------------- attention: one block per (b,h); thread = query row --------
__global__ void attn_kernel() {
    __shared__ float ks[128 * HD];
    __shared__ float vs[128 * HD];
    int b = blockIdx.x >> 3, h = blockIdx.x & 7;
    int n = threadIdx.x;                       // 0..255 query index
    const float* qrow = g_qkv + (size_t)(b * NTOK + n) * (3 * DD) + h * HD;
    float q[HD];
#pragma unroll
    for (int c = 0; c < HD; c++) q[c] = qrow[c] * 0.17677669529663687f; // 1/sqrt(32)
    float mmax = -1e30f, l = 0.f, acc[HD];
#pragma unroll
    for (int c = 0; c < HD; c++) acc[c] = 0.f;

    for (int tile = 0; tile < 2; tile++) {
        __syncthreads();
        for (int i = threadIdx.x; i < 128 * HD; i += 256) {
            int m = i >> 5, c = i & 31;
            const float* base = g_qkv + (size_t)(b * NTOK + tile * 128 + m) * (3 * DD) + h * HD + c;
            ks[i] = base[DD];
            vs[i] = base[2 * DD];
        }
        __syncthreads();
        for (int m = 0; m < 128; m++) {
            float s = 0.f;
#pragma unroll
            for (int c = 0; c < HD; c++) s += q[c] * ks[m * HD + c];
            float nm   = fmaxf(mmax, s);
            float corr = __expf(mmax - nm);
            float p    = __expf(s - nm);
            l = l * corr + p;
#pragma unroll
            for (int c = 0; c < HD; c++) acc[c] = acc[c] * corr + p * vs[m * HD + c];
            mmax = nm;
        }
    }
    float invl = 1.0f / l;
    float* orow = g_att + (size_t)(b * NTOK + n) * DD + h * HD;
#pragma unroll
    for (int c = 0; c < HD; c++) orow[c] = acc[c] * invl;
}

// ---------------- unpatchify: (B*N, 256) -> image ---------------------------
__global__ void unpatchify_kernel() {
    int idx = blockIdx.x * blockDim.x + threadIdx.x;   // b*65536 + y*256 + x
    if (idx >= IMG) return;
    int x = idx & 255, y = (idx >> 8) & 255, b = idx >> 16;
    int hp = y >> 4, py = y & 15, wp = x >> 4, px = x & 15;
    g_img[idx] = g_pix[(size_t)(b * NTOK + hp * 16 + wp) * DD + py * 16 + px];
}

// ---------------- 3x3 SAME conv + conv_b + bp residual ----------------------
__global__ void conv_kernel(const float* __restrict__ cw,
                            const float* __restrict__ cb,
                            float* __restrict__ out) {
    int idx = blockIdx.x * blockDim.x + threadIdx.x;
    if (idx >= IMG) return;
    int x = idx & 255, y = (idx >> 8) & 255, b = idx >> 16;
    const float* im = g_img + (size_t)b * NY * NX;
    float s = 0.f;
#pragma unroll
    for (int ky = 0; ky < 3; ky++) {
        int yy = y + ky - 1;
        if (yy < 0 || yy >= NY) continue;
#pragma unroll
        for (int kx = 0; kx < 3; kx++) {
            int xx = x + kx - 1;
            if (xx < 0 || xx >= NX) continue;
            s += im[yy * NX + xx] * cw[ky * 3 + kx];
        }
    }
    out[idx] = s + cb[0] + g_bp[idx];
}

// ---------------- host orchestration ----------------------------------------
extern "C" void kernel_launch(void* const* d_in, const int* in_sizes, int n_in,
                              void* d_out, int out_size) {
    const float* sino    = (const float*)d_in[0];
    const float* lut     = (const float*)d_in[1];
    const float* patch_w = (const float*)d_in[2];
    const float* patch_b = (const float*)d_in[3];
    const float* pos     = (const float*)d_in[4];
    const float* ln1_g   = (const float*)d_in[5];
    const float* ln1_b   = (const float*)d_in[6];
    const float* wqkv    = (const float*)d_in[7];
    const float* bqkv    = (const float*)d_in[8];
    const float* wo      = (const float*)d_in[9];
    const float* bo      = (const float*)d_in[10];
    const float* ln2_g   = (const float*)d_in[11];
    const float* ln2_b   = (const float*)d_in[12];
    const float* w1      = (const float*)d_in[13];
    const float* b1      = (const float*)d_in[14];
    const float* w2      = (const float*)d_in[15];
    const float* b2      = (const float*)d_in[16];
    const float* proj_w  = (const float*)d_in[17];
    const float* proj_b  = (const float*)d_in[18];
    const float* conv_w  = (const float*)d_in[19];
    const float* conv_b  = (const float*)d_in[20];

    float* out = (float*)d_out;
    float* out_bp = (out_size >= 2 * IMG) ? (out + IMG) : nullptr;

    float *xp, *z, *y, *qkv, *att, *h1, *pix;
    cudaGetSymbolAddress((void**)&xp,  g_x);
    cudaGetSymbolAddress((void**)&z,   g_z);
    cudaGetSymbolAddress((void**)&y,   g_y);
    cudaGetSymbolAddress((void**)&qkv, g_qkv);
    cudaGetSymbolAddress((void**)&att, g_att);
    cudaGetSymbolAddress((void**)&h1,  g_h1);
    cudaGetSymbolAddress((void**)&pix, g_pix);

    // 1) backprojection (also writes bp part of output)
    bp_kernel<<<(NY * NX * 32) / 256, 256>>>(sino, lut, out_bp);
    // 2) patchify + patch embed (+pos)
    patchify_kernel<<<MTOK * DD / 256, 256>>>();
    gemm_kernel<<<dim3(DD / 64, MTOK / 64), 256>>>(xp, patch_w, patch_b, z, pos,
                                                   MTOK, DD, DD, 3);
    // 3) transformer layers
    for (int l = 0; l < LL; l++) {
        ln_kernel<<<MTOK, 256>>>(z, ln1_g + l * DD, ln1_b + l * DD, y);
        gemm_kernel<<<dim3(3 * DD / 64, MTOK / 64), 256>>>(
            y, wqkv + (size_t)l * 3 * DD * DD, bqkv + (size_t)l * 3 * DD, qkv,
            nullptr, MTOK, 3 * DD, DD, 0);
        attn_kernel<<<BB * NHH, 256>>>();
        gemm_kernel<<<dim3(DD / 64, MTOK / 64), 256>>>(
            att, wo + (size_t)l * DD * DD, bo + (size_t)l * DD, z,
            nullptr, MTOK, DD, DD, 2);
        ln_kernel<<<MTOK, 256>>>(z, ln2_g + l * DD, ln2_b + l * DD, y);
        gemm_kernel<<<dim3(4 * DD / 64, MTOK / 64), 256>>>(
            y, w1 + (size_t)l * 4 * DD * DD, b1 + (size_t)l * 4 * DD, h1,
            nullptr, MTOK, 4 * DD, DD, 1);
        gemm_kernel<<<dim3(DD / 64, MTOK / 64), 256>>>(
            h1, w2 + (size_t)l * DD * 4 * DD, b2 + (size_t)l * DD, z,
            nullptr, MTOK, DD, 4 * DD, 2);
    }
    // 4) pixel projection + unpatch + conv + residual
    gemm_kernel<<<dim3(DD / 64, MTOK / 64), 256>>>(z, proj_w, proj_b, pix,
                                                   nullptr, MTOK, DD, DD, 0);
    unpatchify_kernel<<<IMG / 256, 256>>>();
    conv_kernel<<<IMG / 256, 256>>>(conv_w, conv_b, out);
}

// round 2
// speedup vs baseline: 1.5934x; 1.5934x over previous
#include <cuda_runtime.h>
#include <math.h>

#define BB 4
#define NDET 128
#define NT 2048
#define NY 256
#define NX 256
#define DD 256
#define LL 6
#define NHH 8
#define NTOK 256
#define MTOK 1024
#define HD 32
#define IMG (BB*NY*NX)
#define NPIX (NY*NX)

// ---------------- scratch (device globals; no allocation allowed) ----------
__device__ float2 g_lutT  [NDET * NPIX];          // 67MB: lut transposed [d][pixel]
__device__ float  g_bppart[BB * NDET * NPIX];     // 134MB: per-detector partial bp
__device__ float  g_bp  [IMG];
__device__ float  g_x   [MTOK*DD];
__device__ float  g_z   [MTOK*DD];
__device__ float  g_y   [MTOK*DD];
__device__ float  g_qkv [MTOK*3*DD];
__device__ float  g_att [MTOK*DD];
__device__ float  g_h1  [MTOK*4*DD];
__device__ float  g_pix [MTOK*DD];
__device__ float  g_img [IMG];
__device__ float  g_gpart[4 * MTOK * DD];         // split-K GEMM partials
__device__ float  g_pm  [BB*NHH*NTOK*2];          // attn partial max
__device__ float  g_pl  [BB*NHH*NTOK*2];          // attn partial sumexp
__device__ float  g_pacc[BB*NHH*NTOK*2*HD];       // attn partial acc

// ---------------- lut transpose: [pixel][det] -> [det][pixel] --------------
__global__ void lut_transpose_kernel(const float* __restrict__ lut) {
    __shared__ float2 t[32][33];
    const float2* l2 = (const float2*)lut;
    int p0 = blockIdx.x * 32, d0 = blockIdx.y * 32;
    int tx = threadIdx.x, ty = threadIdx.y;
#pragma unroll
    for (int j = ty; j < 32; j += 8)
        t[j][tx] = l2[(size_t)(p0 + j) * NDET + d0 + tx];
    __syncthreads();
#pragma unroll
    for (int j = ty; j < 32; j += 8)
        g_lutT[(size_t)(d0 + j) * NPIX + p0 + tx] = t[tx][j];
}

// ---------------- bp stage: one block per detector, sino rows in smem ------
__global__ void bp_stage_kernel(const float* __restrict__ sino) {
    __shared__ float s[NT * 4];                 // [t][b] interleaved, 32KB
    int d = blockIdx.x;
    for (int i = threadIdx.x; i < NT * 4; i += 256) {
        int b = i >> 11, t = i & (NT - 1);
        s[t * 4 + b] = sino[((size_t)b * NDET + d) * NT + t];
    }
    __syncthreads();
    float apod = 0.5f - 0.5f * cosf(6.283185307179586f * (float)d / 127.0f);
    const float2* lrow = g_lutT + (size_t)d * NPIX;
    float* p0 = g_bppart + (size_t)(0 * NDET + d) * NPIX;
    float* p1 = g_bppart + (size_t)(1 * NDET + d) * NPIX;
    float* p2 = g_bppart + (size_t)(2 * NDET + d) * NPIX;
    float* p3 = g_bppart + (size_t)(3 * NDET + d) * NPIX;
    for (int p = threadIdx.x; p < NPIX; p += 256) {
        float2 ka = lrow[p];
        int kf = (int)ka.x;
        float r0 = 0.f, r1 = 0.f, r2 = 0.f, r3 = 0.f;
        if (kf >= 0 && kf < NT - 1) {
            float a = ka.y;
            float4 s0 = *(const float4*)&s[kf * 4];
            float4 s1 = *(const float4*)&s[kf * 4 + 4];
            r0 = apod * (s0.x + a * (s1.x - s0.x));
            r1 = apod * (s0.y + a * (s1.y - s0.y));
            r2 = apod * (s0.z + a * (s1.z - s0.z));
            r3 = apod * (s0.w + a * (s1.w - s0.w));
        }
        p0[p] = r0; p1[p] = r1; p2[p] = r2; p3[p] = r3;
    }
}

// ---------------- bp reduce: sum over detectors, normalize ------------------
__global__ void bp_reduce_kernel(float* __restrict__ out_bp) {
    int idx = blockIdx.x * blockDim.x + threadIdx.x;   // b*65536 + p
    if (idx >= IMG) return;
    int b = idx >> 16, p = idx & (NPIX - 1);
    const float* base = g_bppart + (size_t)b * NDET * NPIX + p;
    float s = 0.f;
#pragma unroll 8
    for (int d = 0; d < NDET; d++) s += base[(size_t)d * NPIX];
    float v = s * (1.0f / 63.5f);
    g_bp[idx] = v;
    if (out_bp) out_bp[idx] = v;
}

// ---------------- patchify ---------------------------------------------------
__global__ void patchify_kernel() {
    int idx = blockIdx.x * blockDim.x + threadIdx.x;
    if (idx >= MTOK * DD) return;
    int px = idx & 15, py = (idx >> 4) & 15, wp = (idx >> 8) & 15,
        hp = (idx >> 12) & 15, b = idx >> 16;
    g_x[idx] = g_bp[b * NPIX + (hp * 16 + py) * NX + (wp * 16 + px)];
}

// ---------------- GEMM: C = A[M,K] @ W[N,K]^T (+bias/epilogue) --------------
// Direct (gridDim.z==1): mode 0 store, 1 gelu, 2 +=, 3 +pos
// Split-K (gridDim.z>1): raw partial acc into C[z*M*N + ...]
__global__ void gemm_kernel(const float* __restrict__ A,
                            const float* __restrict__ W,
                            const float* __restrict__ bias,
                            float* __restrict__ C,
                            const float* __restrict__ pos,
                            int M, int Nn, int K, int mode, int kchunk) {
    __shared__ float As[16][76];
    __shared__ float Ws[16][76];
    int tid = threadIdx.x;
    int tx = tid & 15, ty = tid >> 4;
    int row0 = blockIdx.y * 64, col0 = blockIdx.x * 64;
    int kb = blockIdx.z * kchunk;
    float acc[4][4];
#pragma unroll
    for (int i = 0; i < 4; i++)
#pragma unroll
        for (int j = 0; j < 4; j++) acc[i][j] = 0.f;

    int lr = tid >> 2, lc = (tid & 3) * 4;
    const float* Ap = A + (size_t)(row0 + lr) * K + kb + lc;
    const float* Wp = W + (size_t)(col0 + lr) * K + kb + lc;

    for (int k0 = 0; k0 < kchunk; k0 += 16) {
        float4 av = *(const float4*)(Ap + k0);
        float4 wv = *(const float4*)(Wp + k0);
        As[lc + 0][lr] = av.x; As[lc + 1][lr] = av.y;
        As[lc + 2][lr] = av.z; As[lc + 3][lr] = av.w;
        Ws[lc + 0][lr] = wv.x; Ws[lc + 1][lr] = wv.y;
        Ws[lc + 2][lr] = wv.z; Ws[lc + 3][lr] = wv.w;
        __syncthreads();
#pragma unroll
        for (int kk = 0; kk < 16; kk++) {
            float4 a = *(const float4*)&As[kk][ty * 4];
            float4 w = *(const float4*)&Ws[kk][tx * 4];
            acc[0][0] += a.x * w.x; acc[0][1] += a.x * w.y;
            acc[0][2] += a.x * w.z; acc[0][3] += a.x * w.w;
            acc[1][0] += a.y * w.x; acc[1][1] += a.y * w.y;
            acc[1][2] += a.y * w.z; acc[1][3] += a.y * w.w;
            acc[2][0] += a.z * w.x; acc[2][1] += a.z * w.y;
            acc[2][2] += a.z * w.z; acc[2][3] += a.z * w.w;
            acc[3][0] += a.w * w.x; acc[3][1] += a.w * w.y;
            acc[3][2] += a.w * w.z; acc[3][3] += a.w * w.w;
        }
        __syncthreads();
    }

    int cc = col0 + tx * 4;
    if (gridDim.z == 1) {
        float4 bv = *(const float4*)&bias[cc];
#pragma unroll
        for (int i = 0; i < 4; i++) {
            int r = row0 + ty * 4 + i;
            float4 v = make_float4(acc[i][0] + bv.x, acc[i][1] + bv.y,
                                   acc[i][2] + bv.z, acc[i][3] + bv.w);
            if (mode == 3) {
                float4 pv = *(const float4*)&pos[(size_t)(r & (NTOK - 1)) * Nn + cc];
                v.x += pv.x; v.y += pv.y; v.z += pv.z; v.w += pv.w;
            }
            if (mode == 1) {
                v.x = 0.5f * v.x * (1.0f + erff(v.x * 0.7071067811865475f));
                v.y = 0.5f * v.y * (1.0f + erff(v.y * 0.7071067811865475f));
                v.z = 0.5f * v.z * (1.0f + erff(v.z * 0.7071067811865475f));
                v.w = 0.5f * v.w * (1.0f + erff(v.w * 0.7071067811865475f));
            }
            float* cp = &C[(size_t)r * Nn + cc];
            if (mode == 2) {
                float4 o = *(float4*)cp;
                v.x += o.x; v.y += o.y; v.z += o.z; v.w += o.w;
            }
            *(float4*)cp = v;
        }
    } else {
        float* Cp = C + (size_t)blockIdx.z * M * Nn;
#pragma unroll
        for (int i = 0; i < 4; i++) {
            int r = row0 + ty * 4 + i;
            *(float4*)&Cp[(size_t)r * Nn + cc] =
                make_float4(acc[i][0], acc[i][1], acc[i][2], acc[i][3]);
        }
    }
}

// ---------------- split-K combine -------------------------------------------
__global__ void combine_kernel(const float* __restrict__ parts, int np,
                               const float* __restrict__ bias,
                               float* __restrict__ C,
                               const float* __restrict__ pos,
                               int mode, int total) {
    int idx = blockIdx.x * blockDim.x + threadIdx.x;
    if (idx >= total) return;
    int c = idx & (DD - 1);
    float v = 0.f;
    for (int p = 0; p < np; p++) v += parts[(size_t)p * total + idx];
    v += bias[c];
    if (mode == 3) v += pos[idx & (NTOK * DD - 1)];
    if (mode == 2) C[idx] += v;
    else           C[idx]  = v;
}

// ---------------- layernorm: one warp per token row -------------------------
__global__ void ln_kernel(const float* __restrict__ in,
                          const float* __restrict__ gam,
                          const float* __restrict__ bet,
                          float* __restrict__ out) {
    int gid  = blockIdx.x * blockDim.x + threadIdx.x;
    int row  = gid >> 5, lane = gid & 31;
    const float4* r4 = (const float4*)(in + (size_t)row * DD);
    float4 a = r4[lane], b = r4[lane + 32];
    float s = (a.x + a.y) + (a.z + a.w) + (b.x + b.y) + (b.z + b.w);
#pragma unroll
    for (int o = 16; o; o >>= 1) s += __shfl_xor_sync(0xffffffffu, s, o);
    float mean = s * (1.0f / DD);
    float dx0 = a.x - mean, dx1 = a.y - mean, dx2 = a.z - mean, dx3 = a.w - mean;
    float dy0 = b.x - mean, dy1 = b.y - mean, dy2 = b.z - mean, dy3 = b.w - mean;
    float sq = dx0*dx0 + dx1*dx1 + dx2*dx2 + dx3*dx3
             + dy0*dy0 + dy1*dy1 + dy2*dy2 + dy3*dy3;
#pragma unroll
    for (int o = 16; o; o >>= 1) sq += __shfl_xor_sync(0xffffffffu, sq, o);
    float rs = rsqrtf(sq * (1.0f / DD) + 1e-5f);
    float4 g0 = ((const float4*)gam)[lane], g1 = ((const float4*)gam)[lane + 32];
    float4 b0 = ((const float4*)bet)[lane], b1 = ((const float4*)bet)[lane + 32];
    float4* o4 = (float4*)(out + (size_t)row * DD);
    o4[lane]      = make_float4(dx0*rs*g0.x + b0.x, dx1*rs*g0.y + b0.y,
                                dx2*rs*g0.z + b0.z, dx3*rs*g0.w + b0.w);
    o4[lane + 32] = make_float4(dy0*rs*g1.x + b1.x, dy1*rs*g1.y + b1.y,
                                dy2*rs*g1.z + b1.z, dy3*rs*g1.w + b1.w);
}

// ---------------- attention: block = (b,h,q-half,kv-half) -------------------
__global__ void attn_kernel() {
    __shared__ float ks [128 * HD];
    __shared__ float vsm[128 * HD];
    int bi  = blockIdx.x;
    int kvh = bi & 1, qh = (bi >> 1) & 1, h = (bi >> 2) & 7, b = bi >> 5;
    for (int i = threadIdx.x; i < 128 * HD; i += 128) {
        int m = i >> 5, c = i & 31;
        const float* base = g_qkv + ((size_t)(b * NTOK + kvh * 128 + m)) * (3 * DD) + h * HD + c;
        ks[i]  = base[DD];
        vsm[i] = base[2 * DD];
    }
    __syncthreads();
    int q = qh * 128 + threadIdx.x;
    const float* qr = g_qkv + (size_t)(b * NTOK + q) * (3 * DD) + h * HD;
    float qv[HD];
#pragma unroll
    for (int c = 0; c < HD; c++) qv[c] = qr[c] * 0.17677669529663687f;
    float mmax = -1e30f, l = 0.f, acc[HD];
#pragma unroll
    for (int c = 0; c < HD; c++) acc[c] = 0.f;
    for (int m = 0; m < 128; m++) {
        const float4* kp = (const float4*)&ks[m * HD];
        float s0 = 0.f, s1 = 0.f, s2 = 0.f, s3 = 0.f;
#pragma unroll
        for (int j = 0; j < 8; j++) {
            float4 k4 = kp[j];
            s0 += qv[j*4+0] * k4.x; s1 += qv[j*4+1] * k4.y;
            s2 += qv[j*4+2] * k4.z; s3 += qv[j*4+3] * k4.w;
        }
        float sc = (s0 + s1) + (s2 + s3);
        float nm   = fmaxf(mmax, sc);
        float corr = __expf(mmax - nm);
        float p    = __expf(sc - nm);
        l = l * corr + p;
        const float4* vp = (const float4*)&vsm[m * HD];
#pragma unroll
        for (int j = 0; j < 8; j++) {
            float4 v4 = vp[j];
            acc[j*4+0] = acc[j*4+0] * corr + p * v4.x;
            acc[j*4+1] = acc[j*4+1] * corr + p * v4.y;
            acc[j*4+2] = acc[j*4+2] * corr + p * v4.z;
            acc[j*4+3] = acc[j*4+3] * corr + p * v4.w;
        }
        mmax = nm;
    }
    int pidx = ((b * NHH + h) * NTOK + q) * 2 + kvh;
    g_pm[pidx] = mmax;
    g_pl[pidx] = l;
    float4* pa = (float4*)&g_pacc[(size_t)pidx * HD];
#pragma unroll
    for (int j = 0; j < 8; j++)
        pa[j] = make_float4(acc[j*4+0], acc[j*4+1], acc[j*4+2], acc[j*4+3]);
}

// ---------------- attention combine ------------------------------------------
__global__ void attn_combine_kernel() {
    int idx = blockIdx.x * blockDim.x + threadIdx.x;   // ((b*8+h)*256+q)*32+c
    if (idx >= BB * NHH * NTOK * HD) return;
    int c = idx & 31, q = (idx >> 5) & 255, h = (idx >> 13) & 7, b = idx >> 16;
    int p0 = ((b * NHH + h) * NTOK + q) * 2;
    float m1 = g_pm[p0], m2 = g_pm[p0 + 1];
    float M  = fmaxf(m1, m2);
    float e1 = __expf(m1 - M), e2 = __expf(m2 - M);
    float L  = e1 * g_pl[p0] + e2 * g_pl[p0 + 1];
    float v  = (e1 * g_pacc[(size_t)p0 * HD + c] +
                e2 * g_pacc[(size_t)(p0 + 1) * HD + c]) / L;
    g_att[(size_t)(b * NTOK + q) * DD + h * HD + c] = v;
}

// ---------------- unpatchify -------------------------------------------------
__global__ void unpatchify_kernel() {
    int idx = blockIdx.x * blockDim.x + threadIdx.x;
    if (idx >= IMG) return;
    int x = idx & 255, y = (idx >> 8) & 255, b = idx >> 16;
    int hp = y >> 4, py = y & 15, wp = x >> 4, px = x & 15;
    g_img[idx] = g_pix[(size_t)(b * NTOK + hp * 16 + wp) * DD + py * 16 + px];
}

// ---------------- 3x3 conv + bias + bp residual ------------------------------
__global__ void conv_kernel(const float* __restrict__ cw,
                            const float* __restrict__ cb,
                            float* __restrict__ out) {
    int idx = blockIdx.x * blockDim.x + threadIdx.x;
    if (idx >= IMG) return;
    int x = idx & 255, y = (idx >> 8) & 255, b = idx >> 16;
    const float* im = g_img + (size_t)b * NPIX;
    float s = 0.f;
#pragma unroll
    for (int ky = 0; ky < 3; ky++) {
        int yy = y + ky - 1;
        if (yy < 0 || yy >= NY) continue;
#pragma unroll
        for (int kx = 0; kx < 3; kx++) {
            int xx = x + kx - 1;
            if (xx < 0 || xx >= NX) continue;
            s += im[yy * NX + xx] * cw[ky * 3 + kx];
        }
    }
    out[idx] = s + cb[0] + g_bp[idx];
}

// ---------------- host orchestration ----------------------------------------
extern "C" void kernel_launch(void* const* d_in, const int* in_sizes, int n_in,
                              void* d_out, int out_size) {
    const float* sino    = (const float*)d_in[0];
    const float* lut     = (const float*)d_in[1];
    const float* patch_w = (const float*)d_in[2];
    const float* patch_b = (const float*)d_in[3];
    const float* pos     = (const float*)d_in[4];
    const float* ln1_g   = (const float*)d_in[5];
    const float* ln1_b   = (const float*)d_in[6];
    const float* wqkv    = (const float*)d_in[7];
    const float* bqkv    = (const float*)d_in[8];
    const float* wo      = (const float*)d_in[9];
    const float* bo      = (const float*)d_in[10];
    const float* ln2_g   = (const float*)d_in[11];
    const float* ln2_b   = (const float*)d_in[12];
    const float* w1      = (const float*)d_in[13];
    const float* b1      = (const float*)d_in[14];
    const float* w2      = (const float*)d_in[15];
    const float* b2      = (const float*)d_in[16];
    const float* proj_w  = (const float*)d_in[17];
    const float* proj_b  = (const float*)d_in[18];
    const float* conv_w  = (const float*)d_in[19];
    const float* conv_b  = (const float*)d_in[20];

    float* out = (float*)d_out;
    float* out_bp = (out_size >= 2 * IMG) ? (out + IMG) : nullptr;

    float *xp, *z, *y, *qkv, *att, *h1, *pix, *gp;
    cudaGetSymbolAddress((void**)&xp,  g_x);
    cudaGetSymbolAddress((void**)&z,   g_z);
    cudaGetSymbolAddress((void**)&y,   g_y);
    cudaGetSymbolAddress((void**)&qkv, g_qkv);
    cudaGetSymbolAddress((void**)&att, g_att);
    cudaGetSymbolAddress((void**)&h1,  g_h1);
    cudaGetSymbolAddress((void**)&pix, g_pix);
    cudaGetSymbolAddress((void**)&gp,  g_gpart);

    const int TOT = MTOK * DD;   // 262144

    // 1) backprojection
    lut_transpose_kernel<<<dim3(NPIX / 32, NDET / 32), dim3(32, 8)>>>(lut);
    bp_stage_kernel<<<NDET, 256>>>(sino);
    bp_reduce_kernel<<<IMG / 256, 256>>>(out_bp);

    // 2) patchify + patch embed (+pos) [split-K 2]
    patchify_kernel<<<TOT / 256, 256>>>();
    gemm_kernel<<<dim3(4, 16, 2), 256>>>(xp, patch_w, patch_b, gp, nullptr,
                                         MTOK, DD, DD, 0, DD / 2);
    combine_kernel<<<TOT / 256, 256>>>(gp, 2, patch_b, z, pos, 3, TOT);

    // 3) transformer layers
    for (int l = 0; l < LL; l++) {
        ln_kernel<<<MTOK / 8, 256>>>(z, ln1_g + l * DD, ln1_b + l * DD, y);
        gemm_kernel<<<dim3(12, 16, 1), 256>>>(
            y, wqkv + (size_t)l * 3 * DD * DD, bqkv + (size_t)l * 3 * DD, qkv,
            nullptr, MTOK, 3 * DD, DD, 0, DD);
        attn_kernel<<<BB * NHH * 4, 128>>>();
        attn_combine_kernel<<<TOT / 256, 256>>>();
        gemm_kernel<<<dim3(4, 16, 2), 256>>>(
            att, wo + (size_t)l * DD * DD, bo + (size_t)l * DD, gp,
            nullptr, MTOK, DD, DD, 0, DD / 2);
        combine_kernel<<<TOT / 256, 256>>>(gp, 2, bo + l * DD, z, nullptr, 2, TOT);
        ln_kernel<<<MTOK / 8, 256>>>(z, ln2_g + l * DD, ln2_b + l * DD, y);
        gemm_kernel<<<dim3(16, 16, 1), 256>>>(
            y, w1 + (size_t)l * 4 * DD * DD, b1 + (size_t)l * 4 * DD, h1,
            nullptr, MTOK, 4 * DD, DD, 1, DD);
        gemm_kernel<<<dim3(4, 16, 4), 256>>>(
            h1, w2 + (size_t)l * DD * 4 * DD, b2 + (size_t)l * DD, gp,
            nullptr, MTOK, DD, 4 * DD, 0, DD);
        combine_kernel<<<TOT / 256, 256>>>(gp, 4, b2 + l * DD, z, nullptr, 2, TOT);
    }

    // 4) pixel projection [split-K 2] + unpatch + conv + residual
    gemm_kernel<<<dim3(4, 16, 2), 256>>>(z, proj_w, proj_b, gp, nullptr,
                                         MTOK, DD, DD, 0, DD / 2);
    combine_kernel<<<TOT / 256, 256>>>(gp, 2, proj_b, pix, nullptr, 0, TOT);
    unpatchify_kernel<<<IMG / 256, 256>>>();
    conv_kernel<<<IMG / 256, 256>>>(conv_w, conv_b, out);
}

// round 5
// speedup vs baseline: 2.3171x; 1.4542x over previous
#include <cuda_runtime.h>
#include <cuda_bf16.h>
#include <cstdint>
#include <math.h>

#define BB 4
#define NDET 128
#define NT 2048
#define NY 256
#define NX 256
#define DD 256
#define LL 6
#define NHH 8
#define NTOK 256
#define MTOK 1024
#define HD 32
#define IMG (BB*NY*NX)
#define NPIX (NY*NX)

// weight buffer offsets (elements)
#define OFF_PATCH 0
#define OFF_QKV   65536
#define OFF_WO    1245184
#define OFF_W1    1638400
#define OFF_W2    3211264
#define OFF_PROJ  4784128
#define WTOT      4849664

// ---------------- scratch (device globals) ----------------------------------
__device__ float          g_bppart[32 * 4 * NPIX];   // 33.5MB
__device__ float          g_bp  [IMG];
__device__ __nv_bfloat16  g_xb  [MTOK*DD];
__device__ float          g_z   [MTOK*DD];
__device__ __nv_bfloat16  g_yb  [MTOK*DD];
__device__ float          g_qkv [MTOK*3*DD];
__device__ __nv_bfloat16  g_attb[MTOK*DD];
__device__ __nv_bfloat16  g_h1b [MTOK*4*DD];
__device__ __nv_bfloat16  g_zb  [MTOK*DD];
__device__ float          g_pix [MTOK*DD];
__device__ float          g_img [IMG];
__device__ __nv_bfloat16  g_wb  [WTOT];
__device__ float          g_gpart[2 * MTOK * DD];    // split-K partials
__device__ float          g_pm  [BB*NHH*NTOK*2];
__device__ float          g_pl  [BB*NHH*NTOK*2];
__device__ float          g_pacc[BB*NHH*NTOK*2*HD];

__device__ __forceinline__ uint32_t pack_bf2(float x, float y) {
    __nv_bfloat162 t = __floats2bfloat162_rn(x, y);
    return *(uint32_t*)&t;
}

// ---------------- weight conversion fp32 -> bf16 -----------------------------
__global__ void wconv_kernel(const float* __restrict__ pw,
                             const float* __restrict__ qkv,
                             const float* __restrict__ wo,
                             const float* __restrict__ w1,
                             const float* __restrict__ w2,
                             const float* __restrict__ prj) {
    int i = blockIdx.x * 256 + threadIdx.x;
    float v;
    if      (i < OFF_QKV)  v = pw [i];
    else if (i < OFF_WO)   v = qkv[i - OFF_QKV];
    else if (i < OFF_W1)   v = wo [i - OFF_WO];
    else if (i < OFF_W2)   v = w1 [i - OFF_W1];
    else if (i < OFF_PROJ) v = w2 [i - OFF_W2];
    else if (i < WTOT)     v = prj[i - OFF_PROJ];
    else return;
    g_wb[i] = __float2bfloat16_rn(v);
}

// ---------------- bp stage: 4 detectors per block, sino staged in smem -------
__global__ void bp_stage4_kernel(const float* __restrict__ sino,
                                 const float* __restrict__ lut) {
    extern __shared__ float s[];                  // [4 det][2048 t][4 b] = 128KB
    int g  = blockIdx.y;                           // detector group
    int d0 = g * 4;
    for (int i = threadIdx.x; i < 4 * NT * 4; i += 256) {
        int t = i & (NT - 1), b = (i >> 11) & 3, dd = i >> 13;
        s[dd * (NT * 4) + t * 4 + b] = sino[((size_t)(b * NDET) + d0 + dd) * NT + t];
    }
    __syncthreads();
    float ap[4];
#pragma unroll
    for (int dd = 0; dd < 4; dd++)
        ap[dd] = 0.5f - 0.5f * cosf(6.283185307179586f * (float)(d0 + dd) / 127.0f);

    int pbase = blockIdx.x * 8192;
    for (int p = pbase + threadIdx.x; p < pbase + 8192; p += 256) {
        const float4* lp = (const float4*)(lut + (size_t)p * 256);
        float4 la = lp[g * 2], lb2 = lp[g * 2 + 1];
        float acc0 = 0.f, acc1 = 0.f, acc2 = 0.f, acc3 = 0.f;
        float kfv[4] = {la.x, la.z, lb2.x, lb2.z};
        float alv[4] = {la.y, la.w, lb2.y, lb2.w};
#pragma unroll
        for (int dd = 0; dd < 4; dd++) {
            int kf = (int)kfv[dd];
            if (kf >= 0 && kf < NT - 1) {
                float a = alv[dd];
                const float* sb = &s[dd * (NT * 4) + kf * 4];
                float4 s0 = *(const float4*)sb;
                float4 s1 = *(const float4*)(sb + 4);
                acc0 += ap[dd] * (s0.x + a * (s1.x - s0.x));
                acc1 += ap[dd] * (s0.y + a * (s1.y - s0.y));
                acc2 += ap[dd] * (s0.z + a * (s1.z - s0.z));
                acc3 += ap[dd] * (s0.w + a * (s1.w - s0.w));
            }
        }
        g_bppart[((size_t)g * 4 + 0) * NPIX + p] = acc0;
        g_bppart[((size_t)g * 4 + 1) * NPIX + p] = acc1;
        g_bppart[((size_t)g * 4 + 2) * NPIX + p] = acc2;
        g_bppart[((size_t)g * 4 + 3) * NPIX + p] = acc3;
    }
}

// ---------------- bp reduce ---------------------------------------------------
__global__ void bp_reduce_kernel(float* __restrict__ out_bp) {
    int idx = blockIdx.x * blockDim.x + threadIdx.x;   // b*NPIX + p
    if (idx >= IMG) return;
    int b = idx >> 16, p = idx & (NPIX - 1);
    float sum = 0.f;
#pragma unroll 8
    for (int gg = 0; gg < 32; gg++)
        sum += g_bppart[((size_t)gg * 4 + b) * NPIX + p];
    float v = sum * (1.0f / 63.5f);
    g_bp[idx] = v;
    if (out_bp) out_bp[idx] = v;
}

// ---------------- patchify -> bf16 -------------------------------------------
__global__ void patchify_kernel() {
    int idx = blockIdx.x * blockDim.x + threadIdx.x;
    if (idx >= MTOK * DD) return;
    int px = idx & 15, py = (idx >> 4) & 15, wp = (idx >> 8) & 15,
        hp = (idx >> 12) & 15, b = idx >> 16;
    g_xb[idx] = __float2bfloat16_rn(
        g_bp[b * NPIX + (hp * 16 + py) * NX + (wp * 16 + px)]);
}

// ---------------- bf16 mma.sync GEMM: C = A[M,K] @ W[N,K]^T + bias ----------
// block tile 64(M) x 128(N), 8 warps (2m x 4n), warp tile 32x32.
// modes: 0 fp32 store | 1 gelu->bf16 | 2 fp32 += | 3 fp32 +bias+pos
// gridDim.z>1: raw partial accumulate into Cf[z*M*Nn + ...]
#define LDSH 40
__global__ void __launch_bounds__(256)
gemm_mma(const __nv_bfloat16* __restrict__ A,
         const __nv_bfloat16* __restrict__ W,
         const float* __restrict__ bias,
         float* __restrict__ Cf,
         __nv_bfloat16* __restrict__ Cb,
         const float* __restrict__ pos,
         int K, int Nn, int mode, int kchunk) {
    __shared__ __nv_bfloat16 As[64 * LDSH];
    __shared__ __nv_bfloat16 Ws[128 * LDSH];
    int tid = threadIdx.x;
    int lane = tid & 31, wid = tid >> 5;
    int wm = wid >> 2, wn = wid & 3;             // 2 x 4 warps
    int m0 = blockIdx.y * 64, n0 = blockIdx.x * 128;
    int kb0 = blockIdx.z * kchunk;

    float acc[2][4][4];
#pragma unroll
    for (int i = 0; i < 2; i++)
#pragma unroll
        for (int j = 0; j < 4; j++)
#pragma unroll
            for (int q = 0; q < 4; q++) acc[i][j][q] = 0.f;

    int lr = tid >> 2, lsg = (tid & 3) * 8;      // load row / seg (halves)

    for (int kt = 0; kt < kchunk; kt += 32) {
        // stage A (64x32) and W (128x32)
        if (tid < 256) {
            *(uint4*)&As[lr * LDSH + lsg] =
                *(const uint4*)(A + (size_t)(m0 + lr) * K + kb0 + kt + lsg);
        }
#pragma unroll
        for (int i = 0; i < 2; i++) {
            int idx = tid + i * 256;
            int r = idx >> 2, sg = (idx & 3) * 8;
            *(uint4*)&Ws[r * LDSH + sg] =
                *(const uint4*)(W + (size_t)(n0 + r) * K + kb0 + kt + sg);
        }
        __syncthreads();
#pragma unroll
        for (int kk = 0; kk < 2; kk++) {
            int kb = kk * 16 + (lane & 3) * 2;
            uint32_t af[2][4];
#pragma unroll
            for (int mf = 0; mf < 2; mf++) {
                int rb = wm * 32 + mf * 16 + (lane >> 2);
                af[mf][0] = *(uint32_t*)&As[rb * LDSH + kb];
                af[mf][1] = *(uint32_t*)&As[(rb + 8) * LDSH + kb];
                af[mf][2] = *(uint32_t*)&As[rb * LDSH + kb + 8];
                af[mf][3] = *(uint32_t*)&As[(rb + 8) * LDSH + kb + 8];
            }
#pragma unroll
            for (int nf = 0; nf < 4; nf++) {
                int nb = wn * 32 + nf * 8 + (lane >> 2);
                uint32_t b0 = *(uint32_t*)&Ws[nb * LDSH + kb];
                uint32_t b1 = *(uint32_t*)&Ws[nb * LDSH + kb + 8];
#pragma unroll
                for (int mf = 0; mf < 2; mf++) {
                    asm volatile(
                        "mma.sync.aligned.m16n8k16.row.col.f32.bf16.bf16.f32 "
                        "{%0,%1,%2,%3}, {%4,%5,%6,%7}, {%8,%9}, {%0,%1,%2,%3};"
                        : "+f"(acc[mf][nf][0]), "+f"(acc[mf][nf][1]),
                          "+f"(acc[mf][nf][2]), "+f"(acc[mf][nf][3])
                        : "r"(af[mf][0]), "r"(af[mf][1]),
                          "r"(af[mf][2]), "r"(af[mf][3]),
                          "r"(b0), "r"(b1));
                }
            }
        }
        __syncthreads();
    }

    // epilogue: c0,c1 at (row, col..col+1); c2,c3 at (row+8, col..col+1)
    bool partial = (gridDim.z > 1);
    float* Cp = partial ? (Cf + (size_t)blockIdx.z * ((size_t)gridDim.y * 64) * Nn)
                        : Cf;
#pragma unroll
    for (int mf = 0; mf < 2; mf++) {
#pragma unroll
        for (int nf = 0; nf < 4; nf++) {
            int row = m0 + wm * 32 + mf * 16 + (lane >> 2);
            int col = n0 + wn * 32 + nf * 8 + (lane & 3) * 2;
#pragma unroll
            for (int half = 0; half < 2; half++) {
                int r = row + half * 8;
                float v0 = acc[mf][nf][half * 2 + 0];
                float v1 = acc[mf][nf][half * 2 + 1];
                if (partial) {
                    *(float2*)&Cp[(size_t)r * Nn + col] = make_float2(v0, v1);
                    continue;
                }
                v0 += bias[col];
                v1 += bias[col + 1];
                if (mode == 3) {
                    const float* pp = &pos[(size_t)(r & (NTOK - 1)) * Nn + col];
                    v0 += pp[0]; v1 += pp[1];
                }
                if (mode == 1) {
                    v0 = 0.5f * v0 * (1.0f + erff(v0 * 0.7071067811865475f));
                    v1 = 0.5f * v1 * (1.0f + erff(v1 * 0.7071067811865475f));
                    *(uint32_t*)&Cb[(size_t)r * Nn + col] = pack_bf2(v0, v1);
                } else {
                    float* cp = &Cf[(size_t)r * Nn + col];
                    if (mode == 2) { v0 += cp[0]; v1 += cp[1]; }
                    *(float2*)cp = make_float2(v0, v1);
                }
            }
        }
    }
}

// ---------------- split-K combine -------------------------------------------
__global__ void combine_kernel(const float* __restrict__ parts, int np,
                               const float* __restrict__ bias,
                               float* __restrict__ C,
                               int Nn, int mode, int total) {
    int idx = blockIdx.x * blockDim.x + threadIdx.x;
    if (idx >= total) return;
    int c = idx % Nn;
    float v = 0.f;
    for (int p = 0; p < np; p++) v += parts[(size_t)p * total + idx];
    v += bias[c];
    if (mode == 2) C[idx] += v;
    else           C[idx]  = v;
}

// ---------------- layernorm: warp per row, bf16 out --------------------------
__global__ void ln_kernel(const float* __restrict__ in,
                          const float* __restrict__ gam,
                          const float* __restrict__ bet,
                          __nv_bfloat16* __restrict__ out) {
    int gid = blockIdx.x * blockDim.x + threadIdx.x;
    int row = gid >> 5, lane = gid & 31;
    const float4* r4 = (const float4*)(in + (size_t)row * DD);
    float4 a = r4[lane * 2], b = r4[lane * 2 + 1];
    float s = (a.x + a.y) + (a.z + a.w) + (b.x + b.y) + (b.z + b.w);
#pragma unroll
    for (int o = 16; o; o >>= 1) s += __shfl_xor_sync(0xffffffffu, s, o);
    float mean = s * (1.0f / DD);
    float d0 = a.x - mean, d1 = a.y - mean, d2 = a.z - mean, d3 = a.w - mean;
    float d4 = b.x - mean, d5 = b.y - mean, d6 = b.z - mean, d7 = b.w - mean;
    float sq = d0*d0 + d1*d1 + d2*d2 + d3*d3 + d4*d4 + d5*d5 + d6*d6 + d7*d7;
#pragma unroll
    for (int o = 16; o; o >>= 1) sq += __shfl_xor_sync(0xffffffffu, sq, o);
    float rs = rsqrtf(sq * (1.0f / DD) + 1e-5f);
    float4 g0 = ((const float4*)gam)[lane * 2], g1 = ((const float4*)gam)[lane * 2 + 1];
    float4 b0 = ((const float4*)bet)[lane * 2], b1 = ((const float4*)bet)[lane * 2 + 1];
    uint4 u;
    u.x = pack_bf2(d0*rs*g0.x + b0.x, d1*rs*g0.y + b0.y);
    u.y = pack_bf2(d2*rs*g0.z + b0.z, d3*rs*g0.w + b0.w);
    u.z = pack_bf2(d4*rs*g1.x + b1.x, d5*rs*g1.y + b1.y);
    u.w = pack_bf2(d6*rs*g1.z + b1.z, d7*rs*g1.w + b1.w);
    *(uint4*)(out + (size_t)row * DD + lane * 8) = u;
}

// ---------------- attention: block = (b,h,q-half,kv-half) -------------------
__global__ void attn_kernel() {
    __shared__ float ks [128 * HD];
    __shared__ float vsm[128 * HD];
    int bi  = blockIdx.x;
    int kvh = bi & 1, qh = (bi >> 1) & 1, h = (bi >> 2) & 7, b = bi >> 5;
    for (int i = threadIdx.x; i < 128 * HD; i += 128) {
        int m = i >> 5, c = i & 31;
        const float* base = g_qkv + ((size_t)(b * NTOK + kvh * 128 + m)) * (3 * DD) + h * HD + c;
        ks[i]  = base[DD];
        vsm[i] = base[2 * DD];
    }
    __syncthreads();
    int q = qh * 128 + threadIdx.x;
    const float* qr = g_qkv + (size_t)(b * NTOK + q) * (3 * DD) + h * HD;
    float qv[HD];
#pragma unroll
    for (int c = 0; c < HD; c++) qv[c] = qr[c] * 0.17677669529663687f;
    float mmax = -1e30f, l = 0.f, acc[HD];
#pragma unroll
    for (int c = 0; c < HD; c++) acc[c] = 0.f;
    for (int m = 0; m < 128; m++) {
        const float4* kp = (const float4*)&ks[m * HD];
        float s0 = 0.f, s1 = 0.f, s2 = 0.f, s3 = 0.f;
#pragma unroll
        for (int j = 0; j < 8; j++) {
            float4 k4 = kp[j];
            s0 += qv[j*4+0] * k4.x; s1 += qv[j*4+1] * k4.y;
            s2 += qv[j*4+2] * k4.z; s3 += qv[j*4+3] * k4.w;
        }
        float sc = (s0 + s1) + (s2 + s3);
        float nm   = fmaxf(mmax, sc);
        float corr = __expf(mmax - nm);
        float p    = __expf(sc - nm);
        l = l * corr + p;
        const float4* vp = (const float4*)&vsm[m * HD];
#pragma unroll
        for (int j = 0; j < 8; j++) {
            float4 v4 = vp[j];
            acc[j*4+0] = acc[j*4+0] * corr + p * v4.x;
            acc[j*4+1] = acc[j*4+1] * corr + p * v4.y;
            acc[j*4+2] = acc[j*4+2] * corr + p * v4.z;
            acc[j*4+3] = acc[j*4+3] * corr + p * v4.w;
        }
        mmax = nm;
    }
    int pidx = ((b * NHH + h) * NTOK + q) * 2 + kvh;
    g_pm[pidx] = mmax;
    g_pl[pidx] = l;
    float4* pa = (float4*)&g_pacc[(size_t)pidx * HD];
#pragma unroll
    for (int j = 0; j < 8; j++)
        pa[j] = make_float4(acc[j*4+0], acc[j*4+1], acc[j*4+2], acc[j*4+3]);
}

// ---------------- attention combine -> bf16 ----------------------------------
__global__ void attn_combine_kernel() {
    int idx = blockIdx.x * blockDim.x + threadIdx.x;
    if (idx >= BB * NHH * NTOK * HD) return;
    int c = idx & 31, q = (idx >> 5) & 255, h = (idx >> 13) & 7, b = idx >> 16;
    int p0 = ((b * NHH + h) * NTOK + q) * 2;
    float m1 = g_pm[p0], m2 = g_pm[p0 + 1];
    float M  = fmaxf(m1, m2);
    float e1 = __expf(m1 - M), e2 = __expf(m2 - M);
    float L  = e1 * g_pl[p0] + e2 * g_pl[p0 + 1];
    float v  = (e1 * g_pacc[(size_t)p0 * HD + c] +
                e2 * g_pacc[(size_t)(p0 + 1) * HD + c]) / L;
    g_attb[(size_t)(b * NTOK + q) * DD + h * HD + c] = __float2bfloat16_rn(v);
}

// ---------------- z -> bf16 ---------------------------------------------------
__global__ void f2b_kernel() {
    int i = blockIdx.x * blockDim.x + threadIdx.x;
    if (i < MTOK * DD) g_zb[i] = __float2bfloat16_rn(g_z[i]);
}

// ---------------- unpatchify --------------------------------------------------
__global__ void unpatchify_kernel() {
    int idx = blockIdx.x * blockDim.x + threadIdx.x;
    if (idx >= IMG) return;
    int x = idx & 255, y = (idx >> 8) & 255, b = idx >> 16;
    int hp = y >> 4, py = y & 15, wp = x >> 4, px = x & 15;
    g_img[idx] = g_pix[(size_t)(b * NTOK + hp * 16 + wp) * DD + py * 16 + px];
}

// ---------------- 3x3 conv + bias + bp residual ------------------------------
__global__ void conv_kernel(const float* __restrict__ cw,
                            const float* __restrict__ cb,
                            float* __restrict__ out) {
    int idx = blockIdx.x * blockDim.x + threadIdx.x;
    if (idx >= IMG) return;
    int x = idx & 255, y = (idx >> 8) & 255, b = idx >> 16;
    const float* im = g_img + (size_t)b * NPIX;
    float s = 0.f;
#pragma unroll
    for (int ky = 0; ky < 3; ky++) {
        int yy = y + ky - 1;
        if (yy < 0 || yy >= NY) continue;
#pragma unroll
        for (int kx = 0; kx < 3; kx++) {
            int xx = x + kx - 1;
            if (xx < 0 || xx >= NX) continue;
            s += im[yy * NX + xx] * cw[ky * 3 + kx];
        }
    }
    out[idx] = s + cb[0] + g_bp[idx];
}

// ---------------- host orchestration ----------------------------------------
extern "C" void kernel_launch(void* const* d_in, const int* in_sizes, int n_in,
                              void* d_out, int out_size) {
    const float* sino    = (const float*)d_in[0];
    const float* lut     = (const float*)d_in[1];
    const float* patch_w = (const float*)d_in[2];
    const float* patch_b = (const float*)d_in[3];
    const float* pos     = (const float*)d_in[4];
    const float* ln1_g   = (const float*)d_in[5];
    const float* ln1_b   = (const float*)d_in[6];
    const float* wqkv    = (const float*)d_in[7];
    const float* bqkv    = (const float*)d_in[8];
    const float* wo      = (const float*)d_in[9];
    const float* bo      = (const float*)d_in[10];
    const float* ln2_g   = (const float*)d_in[11];
    const float* ln2_b   = (const float*)d_in[12];
    const float* w1      = (const float*)d_in[13];
    const float* b1      = (const float*)d_in[14];
    const float* w2      = (const float*)d_in[15];
    const float* b2      = (const float*)d_in[16];
    const float* proj_w  = (const float*)d_in[17];
    const float* proj_b  = (const float*)d_in[18];
    const float* conv_w  = (const float*)d_in[19];
    const float* conv_b  = (const float*)d_in[20];

    float* out = (float*)d_out;
    float* out_bp = (out_size >= 2 * IMG) ? (out + IMG) : nullptr;

    cudaFuncSetAttribute(bp_stage4_kernel, cudaFuncAttributeMaxDynamicSharedMemorySize, 131072);

    __nv_bfloat16 *wb, *xb, *yb, *attb, *h1b, *zb;
    float *z, *qkv, *pix, *gp;
    cudaGetSymbolAddress((void**)&wb,   g_wb);
    cudaGetSymbolAddress((void**)&xb,   g_xb);
    cudaGetSymbolAddress((void**)&yb,   g_yb);
    cudaGetSymbolAddress((void**)&attb, g_attb);
    cudaGetSymbolAddress((void**)&h1b,  g_h1b);
    cudaGetSymbolAddress((void**)&zb,   g_zb);
    cudaGetSymbolAddress((void**)&z,    g_z);
    cudaGetSymbolAddress((void**)&qkv,  g_qkv);
    cudaGetSymbolAddress((void**)&pix,  g_pix);
    cudaGetSymbolAddress((void**)&gp,   g_gpart);

    const int TOT = MTOK * DD;

    // 0) weights -> bf16
    wconv_kernel<<<WTOT / 256, 256>>>(patch_w, wqkv, wo, w1, w2, proj_w);

    // 1) backprojection
    bp_stage4_kernel<<<dim3(8, 32), 256, 131072>>>(sino, lut);
    bp_reduce_kernel<<<IMG / 256, 256>>>(out_bp);

    // 2) patchify + patch embed (+pos)
    patchify_kernel<<<TOT / 256, 256>>>();
    gemm_mma<<<dim3(2, 16), 256>>>(xb, wb + OFF_PATCH, patch_b, z, nullptr,
                                   pos, DD, DD, 3, DD);

    // 3) transformer layers
    for (int l = 0; l < LL; l++) {
        ln_kernel<<<MTOK / 8, 256>>>(z, ln1_g + l * DD, ln1_b + l * DD, yb);
        gemm_mma<<<dim3(6, 16), 256>>>(
            yb, wb + OFF_QKV + (size_t)l * 3 * DD * DD, bqkv + (size_t)l * 3 * DD,
            qkv, nullptr, nullptr, DD, 3 * DD, 0, DD);
        attn_kernel<<<BB * NHH * 4, 128>>>();
        attn_combine_kernel<<<TOT / 256, 256>>>();
        gemm_mma<<<dim3(2, 16), 256>>>(
            attb, wb + OFF_WO + (size_t)l * DD * DD, bo + (size_t)l * DD,
            z, nullptr, nullptr, DD, DD, 2, DD);
        ln_kernel<<<MTOK / 8, 256>>>(z, ln2_g + l * DD, ln2_b + l * DD, yb);
        gemm_mma<<<dim3(8, 16), 256>>>(
            yb, wb + OFF_W1 + (size_t)l * 4 * DD * DD, b1 + (size_t)l * 4 * DD,
            nullptr, h1b, nullptr, DD, 4 * DD, 1, DD);
        gemm_mma<<<dim3(2, 16, 2), 256>>>(
            h1b, wb + OFF_W2 + (size_t)l * DD * 4 * DD, nullptr,
            gp, nullptr, nullptr, 4 * DD, DD, 0, 2 * DD);
        combine_kernel<<<TOT / 256, 256>>>(gp, 2, b2 + l * DD, z, DD, 2, TOT);
    }

    // 4) pixel projection + unpatch + conv + residual
    f2b_kernel<<<TOT / 256, 256>>>();
    gemm_mma<<<dim3(2, 16), 256>>>(zb, wb + OFF_PROJ, proj_b, pix, nullptr,
                                   nullptr, DD, DD, 0, DD);
    unpatchify_kernel<<<IMG / 256, 256>>>();
    conv_kernel<<<IMG / 256, 256>>>(conv_w, conv_b, out);
}